// round 17
// baseline (speedup 1.0000x reference)
#include <cuda_runtime.h>
#include <cuda_fp16.h>
#include <math.h>
#include <stdint.h>

#define BATCH 2
#define NPTS 4096
#define DM 512
#define NH 8
#define DH 64
#define KNB 16
#define ROWS (BATCH * NPTS)   // 8192

// ---------------- scratch (device globals; no allocation allowed) ----------------
__device__ __half g_Qh[ROWS * DM];
__device__ __half g_Kh[ROWS * DM];
__device__ __half g_Vh[ROWS * DM];
__device__ float  g_tmp[ROWS * DM];
__device__ int    g_idx[ROWS * KNB];
__device__ float4 g_pos4[ROWS];
__device__ __half g_Ah[ROWS * DM];            // activation fp16 (feat, later att)
__device__ __half g_Bh[4 * DM * DM];          // transposed weights, fp16
__device__ int    g_count = 0;                // grid barrier arrivals
__device__ int    g_gen   = 0;                // grid barrier generation
__device__ int    g_q2    = 0;                // phase-2 work queue

// ---------------- helpers --------------------------------------------------------
__device__ __forceinline__ uint32_t smem_u32(const void* p) {
    uint32_t a;
    asm("{ .reg .u64 t; cvta.to.shared.u64 t, %1; cvt.u32.u64 %0, t; }"
        : "=r"(a) : "l"(p));
    return a;
}
#define CP16(dst, src) \
    asm volatile("cp.async.cg.shared.global [%0], [%1], 16;" :: "r"(dst), "l"(src))
#define CP_COMMIT() asm volatile("cp.async.commit_group;" ::: "memory")
#define CP_WAIT(n)  asm volatile("cp.async.wait_group %0;" :: "n"(n) : "memory")

__device__ __forceinline__ void ldmx4(uint32_t* r, uint32_t addr) {
    asm volatile("ldmatrix.sync.aligned.m8n8.x4.shared.b16 {%0,%1,%2,%3}, [%4];"
                 : "=r"(r[0]), "=r"(r[1]), "=r"(r[2]), "=r"(r[3]) : "r"(addr));
}
__device__ __forceinline__ void mma16816(float* c, const uint32_t* a, const uint32_t* b) {
    asm volatile(
        "mma.sync.aligned.m16n8k16.row.col.f32.f16.f16.f32 "
        "{%0,%1,%2,%3}, {%4,%5,%6,%7}, {%8,%9}, {%0,%1,%2,%3};"
        : "+f"(c[0]), "+f"(c[1]), "+f"(c[2]), "+f"(c[3])
        : "r"(a[0]), "r"(a[1]), "r"(a[2]), "r"(a[3]), "r"(b[0]), "r"(b[1]));
}
__device__ __forceinline__ uint32_t pkh(__half a, __half b) {
    return ((uint32_t)__half_as_ushort(b) << 16) | __half_as_ushort(a);
}

// ---------------- software grid barrier ------------------------------------------
__device__ __forceinline__ void grid_sync(int nb) {
    __syncthreads();
    if (threadIdx.x == 0) {
        int gen = *(volatile int*)&g_gen;
        __threadfence();
        if (atomicAdd(&g_count, 1) == nb - 1) {
            g_count = 0;
            __threadfence();
            atomicExch(&g_gen, gen + 1);
        } else {
            while (*(volatile int*)&g_gen == gen) __nanosleep(64);
        }
        __threadfence();
    }
    __syncthreads();
}

// ---------------- HMMA fp16 1-term GEMM body -------------------------------------
#define BKC 64
#define NCH (DM / BKC)        // 8
#define ST_A 0
#define ST_B 16384
#define STAGE 32768
#define NSTG 3
#define GEMM_SMEM (NSTG * STAGE)   // 98304

__device__ __forceinline__ void stage_load(uint32_t sb, int slot, int koff, int tid,
                                           const __half* __restrict__ Ah,
                                           const __half* __restrict__ Bh,
                                           int bm, int bn) {
    uint32_t stg = sb + (uint32_t)slot * STAGE;
#pragma unroll
    for (int i = 0; i < 8; i++) {
        int v = i * 256 + tid;          // 0..2047
        int arr = v >> 10;              // 0:A 1:B
        int idx = v & 1023;
        int r = idx >> 3, c = idx & 7;
        const __half* g = arr ? Bh : Ah;
        int rowbase = arr ? bn : bm;
        uint32_t region = arr ? ST_B : ST_A;
        uint32_t dst = stg + region + (uint32_t)(r * 128 + ((c ^ (r & 7)) << 4));
        CP16(dst, &g[(size_t)(rowbase + r) * DM + koff + c * 8]);
    }
    CP_COMMIT();
}

template <bool HALF_OUT>
__device__ __forceinline__ void tc_gemm_body(char* smem,
                                             const __half* __restrict__ Ah,
                                             const __half* __restrict__ Bh,
                                             void* __restrict__ Cp,
                                             int bm, int bn) {
    uint32_t sb = smem_u32(smem);
    int tid = threadIdx.x;             // 256
    int wid = tid >> 5, lane = tid & 31;
    int warp_m = wid & 3, warp_n = wid >> 2;

    float c[2][8][4];
#pragma unroll
    for (int mt = 0; mt < 2; mt++)
#pragma unroll
        for (int nt = 0; nt < 8; nt++)
#pragma unroll
            for (int e = 0; e < 4; e++) c[mt][nt][e] = 0.0f;

    int arow = warp_m * 32 + (lane & 15);
    int akh  = lane >> 4;
    int axor = arow & 7;
    int brow = warp_n * 64 + (lane & 7) + ((lane >> 4) << 3);
    int bkh  = (lane >> 3) & 1;
    int bxor = brow & 7;

    stage_load(sb, 0, 0,   tid, Ah, Bh, bm, bn);
    stage_load(sb, 1, BKC, tid, Ah, Bh, bm, bn);

    for (int kc = 0; kc < NCH; kc++) {
        if (kc == NCH - 1) { CP_WAIT(0); } else { CP_WAIT(1); }
        __syncthreads();
        if (kc + 2 < NCH)
            stage_load(sb, (kc + 2) % NSTG, (kc + 2) * BKC, tid, Ah, Bh, bm, bn);

        uint32_t stg = sb + (uint32_t)(kc % NSTG) * STAGE;
#pragma unroll
        for (int ks = 0; ks < 4; ks++) {
            uint32_t ach = (uint32_t)(((ks * 2 + akh) ^ axor) << 4);
            uint32_t bch = (uint32_t)(((ks * 2 + bkh) ^ bxor) << 4);
            uint32_t ah[2][4];
#pragma unroll
            for (int mt = 0; mt < 2; mt++)
                ldmx4(ah[mt], stg + ST_A + (uint32_t)((arow + mt * 16) * 128) + ach);
#pragma unroll
            for (int npp = 0; npp < 2; npp++) {
                uint32_t bh0[4], bh1[4];
                ldmx4(bh0, stg + ST_B + (uint32_t)((brow + (npp * 2 + 0) * 16) * 128) + bch);
                ldmx4(bh1, stg + ST_B + (uint32_t)((brow + (npp * 2 + 1) * 16) * 128) + bch);
#pragma unroll
                for (int mt = 0; mt < 2; mt++) {
                    mma16816(c[mt][(npp * 2 + 0) * 2 + 0], ah[mt], &bh0[0]);
                    mma16816(c[mt][(npp * 2 + 0) * 2 + 1], ah[mt], &bh0[2]);
                    mma16816(c[mt][(npp * 2 + 1) * 2 + 0], ah[mt], &bh1[0]);
                    mma16816(c[mt][(npp * 2 + 1) * 2 + 1], ah[mt], &bh1[2]);
                }
            }
        }
        __syncthreads();
    }

    int gid = lane >> 2, t4 = lane & 3;
#pragma unroll
    for (int mt = 0; mt < 2; mt++) {
        int r = bm + warp_m * 32 + mt * 16 + gid;
#pragma unroll
        for (int nt = 0; nt < 8; nt++) {
            int col = bn + warp_n * 64 + nt * 8 + t4 * 2;
            if (HALF_OUT) {
                __half* C = (__half*)Cp;
                *(uint32_t*)&C[(size_t)r * DM + col] =
                    pkh(__float2half(c[mt][nt][0]), __float2half(c[mt][nt][1]));
                *(uint32_t*)&C[(size_t)(r + 8) * DM + col] =
                    pkh(__float2half(c[mt][nt][2]), __float2half(c[mt][nt][3]));
            } else {
                float* C = (float*)Cp;
                *(float2*)&C[(size_t)r * DM + col] =
                    make_float2(c[mt][nt][0], c[mt][nt][1]);
                *(float2*)&C[(size_t)(r + 8) * DM + col] =
                    make_float2(c[mt][nt][2], c[mt][nt][3]);
            }
        }
    }
}

// ---------------- kNN job: one CTA, 8 queries, smem positions --------------------
#define QW 8
__device__ __forceinline__ void knn_job(char* smem, int kjob) {
    float4* spos = (float4*)smem;                       // 4096 x 16B = 64KB
    int warp = threadIdx.x >> 5, lane = threadIdx.x & 31;
    int qbase = kjob * QW;
    int q = qbase + warp;
    int b = qbase >> 12;
    int base = b << 12;

    for (int i = threadIdx.x; i < NPTS; i += 256)
        spos[i] = g_pos4[base + i];
    __syncthreads();

    float4 qp = spos[q - base];

    unsigned long long key[KNB + 1];
#pragma unroll
    for (int i = 0; i < KNB + 1; i++) key[i] = 0xFFFFFFFFFFFFFFFFull;
    unsigned long long Tb = 0xFFFFFFFFFFFFFFFFull;

    for (int step = 0; step < NPTS / 32; step++) {
        if ((step & 7) == 0) {
            unsigned long long w = key[KNB];
#pragma unroll
            for (int off = 16; off; off >>= 1) {
                unsigned long long o = __shfl_xor_sync(0xffffffffu, w, off);
                if (o < w) w = o;
            }
            Tb = w;
        }
        int j = step * 32 + lane;
        float4 p = spos[j];
        float dx = qp.x - p.x;
        float dy = qp.y - p.y;
        float dz = qp.z - p.z;
        float d = fmaf(dx, dx, fmaf(dy, dy, dz * dz));
        unsigned long long kk =
            ((unsigned long long)__float_as_uint(d) << 32) | (unsigned)j;
        if (kk < Tb) {
#pragma unroll
            for (int p2 = KNB; p2 >= 1; p2--) {
                unsigned long long lower = key[p2 - 1];
                unsigned long long cur   = key[p2];
                key[p2] = (kk >= cur) ? cur : ((kk >= lower) ? kk : lower);
            }
            key[0] = (kk < key[0]) ? kk : key[0];
        }
    }

    __syncthreads();
    unsigned long long (*smrg)[32][KNB + 2] =
        (unsigned long long (*)[32][KNB + 2])smem;
#pragma unroll
    for (int i = 0; i < KNB + 1; i++) smrg[warp][lane][i] = key[i];
    smrg[warp][lane][KNB + 1] = 0xFFFFFFFFFFFFFFFFull;
    __syncwarp();

    int p = 0;
    unsigned long long head = smrg[warp][lane][0];
    for (int out = 0; out < KNB + 1; out++) {
        unsigned long long m = head;
#pragma unroll
        for (int off = 16; off; off >>= 1) {
            unsigned long long o = __shfl_xor_sync(0xffffffffu, m, off);
            if (o < m) m = o;
        }
        if (out > 0 && lane == 0)
            g_idx[q * KNB + out - 1] = (int)(unsigned)m;
        if (head == m) { p++; head = smrg[warp][lane][p]; }
    }
}

// ---------------- attn job: 8 (row,head) warps -----------------------------------
__device__ __forceinline__ void attn_job(int job, const float* __restrict__ Wpos,
                                         const float* __restrict__ bpos, float invT) {
    int warp = threadIdx.x >> 5, lane = threadIdx.x & 31;
    int gw   = job * 8 + warp;
    int row  = gw >> 3;
    int h    = gw & 7;
    int b    = row >> 12;
    int base = (b << 12);

    int j = 0;
    float rx = 0.f, ry = 0.f, rz = 0.f;
    float4 qp = g_pos4[row];
    if (lane < KNB) {
        j  = g_idx[row * KNB + lane];
        float4 p = g_pos4[base + j];
        rx = qp.x - p.x; ry = qp.y - p.y; rz = qp.z - p.z;
    }

    int jks[KNB];
#pragma unroll
    for (int k = 0; k < KNB; k++)
        jks[k] = __shfl_sync(0xffffffffu, j, k);

    __half2 kvh[KNB], vvh[KNB];
#pragma unroll
    for (int k = 0; k < KNB; k++)
        kvh[k] = *(const __half2*)&g_Kh[(size_t)(base + jks[k]) * DM + h * DH + 2 * lane];
#pragma unroll
    for (int k = 0; k < KNB; k++)
        vvh[k] = *(const __half2*)&g_Vh[(size_t)(base + jks[k]) * DM + h * DH + 2 * lane];

    float2 q = __half22float2(*(const __half2*)&g_Qh[(size_t)row * DM + h * DH + 2 * lane]);
    q.x *= invT; q.y *= invT;
    float2 w0 = *(const float2*)&Wpos[0 * 128 + 2 * lane];
    float2 w1 = *(const float2*)&Wpos[1 * 128 + 2 * lane];
    float2 w2 = *(const float2*)&Wpos[2 * 128 + 2 * lane];
    float2 bp = *(const float2*)&bpos[2 * lane];

    float pa = fmaf(q.x, w0.x, q.y * w0.y);
    float pb = fmaf(q.x, w1.x, q.y * w1.y);
    float pc = fmaf(q.x, w2.x, q.y * w2.y);
    float pd = fmaf(q.x, bp.x, q.y * bp.y);
#pragma unroll
    for (int off = 16; off; off >>= 1) {
        pa += __shfl_xor_sync(0xffffffffu, pa, off);
        pb += __shfl_xor_sync(0xffffffffu, pb, off);
        pc += __shfl_xor_sync(0xffffffffu, pc, off);
        pd += __shfl_xor_sync(0xffffffffu, pd, off);
    }

    float myscore = 0.0f;
#pragma unroll
    for (int k = 0; k < KNB / 2; k++) {
        float2 ka = __half22float2(kvh[k]);
        float2 kb = __half22float2(kvh[k + 8]);
        float s0 = fmaf(q.x, ka.x, q.y * ka.y);
        float s1 = fmaf(q.x, kb.x, q.y * kb.y);
#pragma unroll
        for (int off = 16; off; off >>= 1) {
            s0 += __shfl_xor_sync(0xffffffffu, s0, off);
            s1 += __shfl_xor_sync(0xffffffffu, s1, off);
        }
        if (lane == k)     myscore = s0;
        if (lane == k + 8) myscore = s1;
    }
    myscore += fmaf(rx, pa, fmaf(ry, pb, fmaf(rz, pc, pd)));

    float sc = (lane < KNB) ? myscore : -INFINITY;
    float m = sc;
#pragma unroll
    for (int off = 8; off; off >>= 1)
        m = fmaxf(m, __shfl_xor_sync(0xffffffffu, m, off));
    float e = (lane < KNB) ? __expf(sc - m) : 0.0f;
    float sum = e;
#pragma unroll
    for (int off = 8; off; off >>= 1)
        sum += __shfl_xor_sync(0xffffffffu, sum, off);
    float w = e / sum;

    float2 acc = make_float2(0.f, 0.f);
#pragma unroll
    for (int k = 0; k < KNB; k++) {
        float wk = __shfl_sync(0xffffffffu, w, k);
        float2 v = __half22float2(vvh[k]);
        acc.x = fmaf(wk, v.x, acc.x);
        acc.y = fmaf(wk, v.y, acc.y);
    }
    size_t off = (size_t)row * DM + h * DH + 2 * lane;
    *(uint32_t*)&g_Ah[off] = pkh(__float2half(acc.x), __float2half(acc.y));
}

// ---------------- ln job: 8 rows, warp per row -----------------------------------
__device__ __forceinline__ void ln_job(int job, const float* __restrict__ feat,
                                       const float* __restrict__ bo,
                                       const float* __restrict__ gamma,
                                       const float* __restrict__ beta,
                                       float* __restrict__ out) {
    int warp = threadIdx.x >> 5, lane = threadIdx.x & 31;
    int row  = job * 8 + warp;

    float4 x[4];
    float s = 0.0f;
#pragma unroll
    for (int i = 0; i < 4; i++) {
        int col = lane * 4 + i * 128;
        float4 a = *(const float4*)&g_tmp[(size_t)row * DM + col];
        float4 f = *(const float4*)&feat[(size_t)row * DM + col];
        float4 bb = *(const float4*)&bo[col];
        x[i] = make_float4(a.x + f.x + bb.x, a.y + f.y + bb.y,
                           a.z + f.z + bb.z, a.w + f.w + bb.w);
        s += x[i].x + x[i].y + x[i].z + x[i].w;
    }
#pragma unroll
    for (int o = 16; o; o >>= 1) s += __shfl_xor_sync(0xffffffffu, s, o);
    float mu = s * (1.0f / DM);

    float v = 0.0f;
#pragma unroll
    for (int i = 0; i < 4; i++) {
        float dx = x[i].x - mu, dy = x[i].y - mu, dz = x[i].z - mu, dw = x[i].w - mu;
        v += dx * dx + dy * dy + dz * dz + dw * dw;
    }
#pragma unroll
    for (int o = 16; o; o >>= 1) v += __shfl_xor_sync(0xffffffffu, v, o);
    float rs = rsqrtf(v * (1.0f / DM) + 1e-5f);

#pragma unroll
    for (int i = 0; i < 4; i++) {
        int col = lane * 4 + i * 128;
        float4 g = *(const float4*)&gamma[col];
        float4 be = *(const float4*)&beta[col];
        float4 o4;
        o4.x = (x[i].x - mu) * rs * g.x + be.x;
        o4.y = (x[i].y - mu) * rs * g.y + be.y;
        o4.z = (x[i].z - mu) * rs * g.z + be.z;
        o4.w = (x[i].w - mu) * rs * g.w + be.w;
        *(float4*)&out[(size_t)row * DM + col] = o4;
    }
}

// ---------------- persistent mega-kernel -----------------------------------------
__global__ __launch_bounds__(256, 2) void mega_kernel(
    const float* __restrict__ pos,  const float* __restrict__ feat,
    const float* __restrict__ W0,   const float* __restrict__ W1,
    const float* __restrict__ W2,   const float* __restrict__ W3,
    const float* __restrict__ bo,   const float* __restrict__ Wpos,
    const float* __restrict__ bpos, const float* __restrict__ temp,
    const float* __restrict__ gamma,const float* __restrict__ beta,
    float* __restrict__ out, int nb)
{
    extern __shared__ __align__(128) char smem[];
    __shared__ int s_job;
    __shared__ float t[32][33];
    int bid = blockIdx.x, tid = threadIdx.x;

    // ---- phase 1: prep (feat->fp16, weight transpose->fp16, pos4) ----
    for (int job = bid; job < 512 + 1024 + 32; job += nb) {
        if (job < 512) {
            size_t base = (size_t)job * 2048 + tid;
            float4 v[8];
#pragma unroll
            for (int i = 0; i < 8; i++)
                v[i] = *(const float4*)&feat[(base + i * 256) * 4];
#pragma unroll
            for (int i = 0; i < 8; i++) {
                uint2 h;
                h.x = pkh(__float2half(v[i].x), __float2half(v[i].y));
                h.y = pkh(__float2half(v[i].z), __float2half(v[i].w));
                *(uint2*)&g_Ah[(base + i * 256) * 4] = h;
            }
        } else if (job < 512 + 1024) {
            int id = job - 512;
            int z = id >> 8;
            int by = ((id >> 4) & 15) * 32, bx = (id & 15) * 32;
            const float* src = (z == 0) ? W0 : (z == 1) ? W1 : (z == 2) ? W2 : W3;
            size_t zoff = (size_t)z * DM * DM;
            int tx = tid & 31, ty = tid >> 5;
            __syncthreads();
#pragma unroll
            for (int i = 0; i < 32; i += 8)
                t[ty + i][tx] = src[(size_t)(by + ty + i) * DM + bx + tx];
            __syncthreads();
#pragma unroll
            for (int i = 0; i < 32; i += 8)
                g_Bh[zoff + (size_t)(bx + ty + i) * DM + by + tx] =
                    __float2half(t[tx][ty + i]);
        } else {
            int i = (job - 512 - 1024) * 256 + tid;
            g_pos4[i] = make_float4(pos[i * 3 + 0], pos[i * 3 + 1], pos[i * 3 + 2], 0.0f);
        }
    }
    if (bid == 0 && tid == 0) g_q2 = 0;   // reset phase-2 queue (before barrier)
    grid_sync(nb);

    // ---- phase 2: QKV GEMMs + kNN via dynamic work queue ----
    while (true) {
        __syncthreads();
        if (tid == 0) s_job = atomicAdd(&g_q2, 1);
        __syncthreads();
        int job = s_job;
        if (job >= 768 + 1024) break;
        if (job < 768) {
            int z  = job >> 8;
            int rem = job & 255;
            int bm = (rem >> 2) * 128, bn = (rem & 3) * 128;
            __half* C = (z == 0) ? g_Qh : (z == 1) ? g_Kh : g_Vh;
            tc_gemm_body<true>(smem, g_Ah, g_Bh + (size_t)z * DM * DM, C, bm, bn);
        } else {
            knn_job(smem, job - 768);
        }
    }
    grid_sync(nb);

    // ---- phase 3: attention ----
    float invT = 1.0f / temp[0];
    for (int job = bid; job < ROWS; job += nb)      // 8192 jobs x 8 warps
        attn_job(job, Wpos, bpos, invT);
    grid_sync(nb);

    // ---- phase 4: Wo GEMM ----
    for (int job = bid; job < 256; job += nb) {
        int bm = (job >> 2) * 128, bn = (job & 3) * 128;
        __syncthreads();
        tc_gemm_body<false>(smem, g_Ah, g_Bh + (size_t)3 * DM * DM, g_tmp, bm, bn);
    }
    grid_sync(nb);

    // ---- phase 5: +bo, +residual, LayerNorm ----
    for (int job = bid; job < ROWS / 8; job += nb)  // 1024 jobs
        ln_job(job, feat, bo, gamma, beta, out);
}

// ---------------- launch ---------------------------------------------------------
extern "C" void kernel_launch(void* const* d_in, const int* in_sizes, int n_in,
                              void* d_out, int out_size) {
    const float* pos   = (const float*)d_in[0];
    const float* feat  = (const float*)d_in[1];
    const float* Wq    = (const float*)d_in[3];
    const float* Wk    = (const float*)d_in[4];
    const float* Wv    = (const float*)d_in[5];
    const float* Wo    = (const float*)d_in[6];
    const float* bo    = (const float*)d_in[7];
    const float* Wpos  = (const float*)d_in[8];
    const float* bpos  = (const float*)d_in[9];
    const float* temp  = (const float*)d_in[10];
    const float* gamma = (const float*)d_in[11];
    const float* beta  = (const float*)d_in[12];
    float* out = (float*)d_out;

    static int nb = 0;
    if (nb == 0) {
        int sms = 0;
        cudaDeviceGetAttribute(&sms, cudaDevAttrMultiProcessorCount, 0);
        nb = 2 * sms;
        cudaFuncSetAttribute(mega_kernel,
                             cudaFuncAttributeMaxDynamicSharedMemorySize, GEMM_SMEM);
    }

    mega_kernel<<<nb, 256, GEMM_SMEM>>>(pos, feat, Wq, Wk, Wv, Wo, bo,
                                        Wpos, bpos, temp, gamma, beta, out, nb);
}